// round 1
// baseline (speedup 1.0000x reference)
#include <cuda_runtime.h>
#include <math.h>

#define NATOM 32768
#define MNBR 12
#define DIM 64
#define FNBR 41
#define ORIG 92
#define TWO_D 128
#define KTOT 169
#define KNB 105
#define NCRY 512
#define NA 64
#define CNT1F (393216.0f)
#define CNT2F (32768.0f)
#define EPSBN 1e-5f

// ---------------- scratch (device globals; no allocation) ----------------
__device__ float g_x[2][NATOM * DIM];
__device__ float g_zself[NATOM * TWO_D];
__device__ float g_z[NATOM * MNBR * TWO_D];          // 201 MB
__device__ float g_summed[NATOM * DIM];
__device__ float g_G[NCRY * NA * 6 * DIM];           // 50 MB
__device__ float g_Wt[3 * KTOT * TWO_D];             // conv_W transposed [l][k][o]
__device__ float g_embT[ORIG * DIM];                 // [k][d]
__device__ float g_bilT[DIM * 6 * DIM];              // [d][o*64+k]
__device__ float g_fcaT[DIM * ORIG];                 // [k][c]
__device__ float g_s1[TWO_D], g_ss1[TWO_D], g_s2[DIM], g_ss2[DIM];

__device__ __forceinline__ float softplusf(float v) {
    return v > 20.0f ? v : log1pf(expf(v));
}

// ---------------- prep: transposes for coalesced GEMM B loads ----------------
__global__ void prep_kernel(const float* __restrict__ conv_W,
                            const float* __restrict__ embed_W,
                            const float* __restrict__ bil_W,
                            const float* __restrict__ fca_W) {
    int idx = blockIdx.x * blockDim.x + threadIdx.x;
    if (idx < 3 * KTOT * TWO_D) {
        int l = idx / (KTOT * TWO_D);
        int r = idx % (KTOT * TWO_D);
        int k = r / TWO_D, o = r % TWO_D;
        g_Wt[idx] = conv_W[(l * TWO_D + o) * KTOT + k];
        return;
    }
    int i2 = idx - 3 * KTOT * TWO_D;
    if (i2 >= 0 && i2 < ORIG * DIM) {
        int k = i2 / DIM, d = i2 % DIM;
        g_embT[i2] = embed_W[d * ORIG + k];
        return;
    }
    int i3 = i2 - ORIG * DIM;
    if (i3 >= 0 && i3 < DIM * 6 * DIM) {
        int d = i3 / (6 * DIM), ok = i3 % (6 * DIM);
        int o = ok / DIM, k = ok % DIM;
        g_bilT[i3] = bil_W[(o * DIM + d) * DIM + k];
        return;
    }
    int i4 = i3 - DIM * 6 * DIM;
    if (i4 >= 0 && i4 < DIM * ORIG) {
        int k = i4 / ORIG, c = i4 % ORIG;
        g_fcaT[i4] = fca_W[c * DIM + k];
    }
}

// ---------------- embedding: x = atom_fea @ embed_W^T  (K=92) ----------------
__global__ __launch_bounds__(256) void embed_kernel(const float* __restrict__ atom_fea) {
    __shared__ float As[64 * ORIG];
    __shared__ float Ws[ORIG * DIM];
    int t = threadIdx.x;
    int rb = blockIdx.x * 64;
    for (int e = t; e < ORIG * DIM; e += 256) Ws[e] = g_embT[e];
    int warp = t >> 5, lane = t & 31;
    for (int m = warp; m < 64; m += 8) {
        const float* row = atom_fea + (rb + m) * ORIG;
        As[m * ORIG + lane] = row[lane];
        As[m * ORIG + 32 + lane] = row[32 + lane];
        if (lane < ORIG - 64) As[m * ORIG + 64 + lane] = row[64 + lane];
    }
    __syncthreads();
    int ty = t >> 5, tx = t & 31;
    float acc[8][2];
#pragma unroll
    for (int i = 0; i < 8; i++) { acc[i][0] = 0.f; acc[i][1] = 0.f; }
    for (int k = 0; k < ORIG; k++) {
        float2 b = *(const float2*)&Ws[k * DIM + tx * 2];
#pragma unroll
        for (int i = 0; i < 8; i++) {
            float a = As[(ty * 8 + i) * ORIG + k];
            acc[i][0] = fmaf(a, b.x, acc[i][0]);
            acc[i][1] = fmaf(a, b.y, acc[i][1]);
        }
    }
#pragma unroll
    for (int i = 0; i < 8; i++)
        *(float2*)&g_x[0][(rb + ty * 8 + i) * DIM + tx * 2] = make_float2(acc[i][0], acc[i][1]);
}

// ---------------- per-layer stat zeroing ----------------
__global__ void zero_stats() {
    int t = threadIdx.x;
    if (t < TWO_D) { g_s1[t] = 0.f; g_ss1[t] = 0.f; }
    if (t < DIM)   { g_s2[t] = 0.f; g_ss2[t] = 0.f; }
}

// ---------------- zself[n,o] = b[o] + W[:, :64] . x[n]  (K=64 GEMM) ----------------
__global__ __launch_bounds__(256) void zself_kernel(int l, int buf,
                                                    const float* __restrict__ conv_b) {
    extern __shared__ float sm[];
    float* Ws = sm;                // [64][128]
    float* As = sm + 64 * TWO_D;   // [64][64]
    int t = threadIdx.x;
    int rb = blockIdx.x * 64;
    const float* x = g_x[buf];
    for (int e = t; e < 64 * TWO_D; e += 256) Ws[e] = g_Wt[l * KTOT * TWO_D + e];
    int warp = t >> 5, lane = t & 31;
    for (int m = warp; m < 64; m += 8) {
        As[m * 64 + lane]      = x[(rb + m) * DIM + lane];
        As[m * 64 + 32 + lane] = x[(rb + m) * DIM + 32 + lane];
    }
    __syncthreads();
    int ty = t >> 5, tx = t & 31;
    float acc[8][4];
#pragma unroll
    for (int i = 0; i < 8; i++)
#pragma unroll
        for (int c = 0; c < 4; c++) acc[i][c] = conv_b[l * TWO_D + tx * 4 + c];
    for (int k = 0; k < 64; k++) {
        float4 b = *(const float4*)&Ws[k * TWO_D + tx * 4];
#pragma unroll
        for (int i = 0; i < 8; i++) {
            float a = As[(ty * 8 + i) * 64 + k];
            acc[i][0] = fmaf(a, b.x, acc[i][0]);
            acc[i][1] = fmaf(a, b.y, acc[i][1]);
            acc[i][2] = fmaf(a, b.z, acc[i][2]);
            acc[i][3] = fmaf(a, b.w, acc[i][3]);
        }
    }
#pragma unroll
    for (int i = 0; i < 8; i++)
        *(float4*)&g_zself[(rb + ty * 8 + i) * TWO_D + tx * 4] =
            make_float4(acc[i][0], acc[i][1], acc[i][2], acc[i][3]);
}

// ---------------- main conv GEMM: z[nm,o] = zself + [x[nbr]|nbr_fea] @ W2^T, + BN1 stats ----------------
#define ASP 108
__global__ __launch_bounds__(256) void convz_kernel(int l, int buf,
                                                    const float* __restrict__ nbr_fea,
                                                    const int* __restrict__ nbr_idx) {
    extern __shared__ float sm[];
    float* Ws = sm;                 // [105][128]
    float* As = sm + KNB * TWO_D;   // [64][108]
    __shared__ int nbr_s[64];
    int t = threadIdx.x;
    int rb = blockIdx.x * 64;
    const float* x = g_x[buf];
    if (t < 64) nbr_s[t] = nbr_idx[rb + t];
    for (int e = t; e < KNB * TWO_D; e += 256)
        Ws[e] = g_Wt[l * KTOT * TWO_D + DIM * TWO_D + e];
    __syncthreads();
    int warp = t >> 5, lane = t & 31;
    for (int m = warp; m < 64; m += 8) {
        int nbr = nbr_s[m];
        As[m * ASP + lane]      = x[nbr * DIM + lane];
        As[m * ASP + 32 + lane] = x[nbr * DIM + 32 + lane];
        const float* nf = nbr_fea + (long)(rb + m) * FNBR;
        As[m * ASP + 64 + lane] = nf[lane];
        if (lane < FNBR - 32) As[m * ASP + 96 + lane] = nf[32 + lane];
    }
    __syncthreads();
    int ty = t >> 5, tx = t & 31;
    float acc[8][4];
#pragma unroll
    for (int i = 0; i < 8; i++)
#pragma unroll
        for (int c = 0; c < 4; c++) acc[i][c] = 0.f;
    for (int k = 0; k < KNB; k++) {
        float4 b = *(const float4*)&Ws[k * TWO_D + tx * 4];
#pragma unroll
        for (int i = 0; i < 8; i++) {
            float a = As[(ty * 8 + i) * ASP + k];
            acc[i][0] = fmaf(a, b.x, acc[i][0]);
            acc[i][1] = fmaf(a, b.y, acc[i][1]);
            acc[i][2] = fmaf(a, b.z, acc[i][2]);
            acc[i][3] = fmaf(a, b.w, acc[i][3]);
        }
    }
    float s[4] = {0.f, 0.f, 0.f, 0.f}, q[4] = {0.f, 0.f, 0.f, 0.f};
#pragma unroll
    for (int i = 0; i < 8; i++) {
        int row = rb + ty * 8 + i;
        int n = row / MNBR;
        float4 zs = *(const float4*)&g_zself[n * TWO_D + tx * 4];
        float4 v;
        v.x = acc[i][0] + zs.x; v.y = acc[i][1] + zs.y;
        v.z = acc[i][2] + zs.z; v.w = acc[i][3] + zs.w;
        *(float4*)&g_z[(long)row * TWO_D + tx * 4] = v;
        s[0] += v.x; q[0] += v.x * v.x;
        s[1] += v.y; q[1] += v.y * v.y;
        s[2] += v.z; q[2] += v.z * v.z;
        s[3] += v.w; q[3] += v.w * v.w;
    }
    __syncthreads();   // As no longer needed; reuse as reduction buffer
    float* redS = As;
    float* redQ = As + 1024;
#pragma unroll
    for (int c = 0; c < 4; c++) {
        redS[ty * TWO_D + tx * 4 + c] = s[c];
        redQ[ty * TWO_D + tx * 4 + c] = q[c];
    }
    __syncthreads();
    if (t < TWO_D) {
        float tot = 0.f;
#pragma unroll
        for (int w = 0; w < 8; w++) tot += redS[w * TWO_D + t];
        atomicAdd(&g_s1[t], tot);
    } else {
        int o = t - TWO_D;
        float tot = 0.f;
#pragma unroll
        for (int w = 0; w < 8; w++) tot += redQ[w * TWO_D + o];
        atomicAdd(&g_ss1[o], tot);
    }
}

// ---------------- BN1 + gate + sum over neighbors, BN2 stats ----------------
__global__ __launch_bounds__(64) void reduce_kernel(int l,
                                                    const float* __restrict__ bn1_g,
                                                    const float* __restrict__ bn1_b) {
    int d = threadIdx.x;
    float inv = 1.0f / CNT1F;
    float mf = g_s1[d] * inv;
    float vf = g_ss1[d] * inv - mf * mf;
    float sc_f = rsqrtf(vf + EPSBN) * bn1_g[l * TWO_D + d];
    float sh_f = bn1_b[l * TWO_D + d] - mf * sc_f;
    float mc = g_s1[64 + d] * inv;
    float vc = g_ss1[64 + d] * inv - mc * mc;
    float sc_c = rsqrtf(vc + EPSBN) * bn1_g[l * TWO_D + 64 + d];
    float sh_c = bn1_b[l * TWO_D + 64 + d] - mc * sc_c;

    float ls = 0.f, lq = 0.f;
    int n0 = blockIdx.x * 8;
    for (int a = 0; a < 8; a++) {
        int n = n0 + a;
        const float* zr = g_z + (long)n * MNBR * TWO_D;
        float accv = 0.f;
#pragma unroll
        for (int m = 0; m < MNBR; m++) {
            float zf = zr[m * TWO_D + d];
            float zc = zr[m * TWO_D + 64 + d];
            float fv = zf * sc_f + sh_f;
            float cv = zc * sc_c + sh_c;
            float sig = 1.0f / (1.0f + expf(-fv));
            accv += sig * softplusf(cv);
        }
        g_summed[n * DIM + d] = accv;
        ls += accv; lq += accv * accv;
    }
    atomicAdd(&g_s2[d], ls);
    atomicAdd(&g_ss2[d], lq);
}

// ---------------- BN2 + residual softplus -> x_out ----------------
__global__ __launch_bounds__(256) void bnres_kernel(int l, int buf,
                                                    const float* __restrict__ bn2_g,
                                                    const float* __restrict__ bn2_b) {
    int gid = blockIdx.x * 256 + threadIdx.x;
    int d = gid & 63;
    float inv = 1.0f / CNT2F;
    float m2 = g_s2[d] * inv;
    float v2 = g_ss2[d] * inv - m2 * m2;
    float sc = rsqrtf(v2 + EPSBN) * bn2_g[l * DIM + d];
    float sh = bn2_b[l * DIM + d] - m2 * sc;
    float v = g_x[buf][gid] + g_summed[gid] * sc + sh;
    g_x[1 - buf][gid] = softplusf(v);
}

// ---------------- G[bi, o*64+k] = f[bi,:] @ bilT  (GEMM 32768 x 384, K=64) ----------------
__global__ __launch_bounds__(256) void gmat_kernel(int buf, const int* __restrict__ cidx) {
    extern __shared__ float sm[];
    float* Ws = sm;                // [64][128]
    float* As = sm + 64 * TWO_D;   // [64][64]
    __shared__ int cid_s[64];
    int t = threadIdx.x;
    int rb = blockIdx.x * 64;
    int co = blockIdx.y * 128;
    const float* x = g_x[buf];
    if (t < 64) cid_s[t] = cidx[rb + t];
    for (int e = t; e < 64 * TWO_D; e += 256) {
        int k = e >> 7, oc = e & 127;
        Ws[e] = g_bilT[k * 384 + co + oc];
    }
    __syncthreads();
    int warp = t >> 5, lane = t & 31;
    for (int m = warp; m < 64; m += 8) {
        int a = cid_s[m];
        As[m * 64 + lane]      = x[a * DIM + lane];
        As[m * 64 + 32 + lane] = x[a * DIM + 32 + lane];
    }
    __syncthreads();
    int ty = t >> 5, tx = t & 31;
    float acc[8][4];
#pragma unroll
    for (int i = 0; i < 8; i++)
#pragma unroll
        for (int c = 0; c < 4; c++) acc[i][c] = 0.f;
    for (int k = 0; k < 64; k++) {
        float4 b = *(const float4*)&Ws[k * TWO_D + tx * 4];
#pragma unroll
        for (int i = 0; i < 8; i++) {
            float a = As[(ty * 8 + i) * 64 + k];
            acc[i][0] = fmaf(a, b.x, acc[i][0]);
            acc[i][1] = fmaf(a, b.y, acc[i][1]);
            acc[i][2] = fmaf(a, b.z, acc[i][2]);
            acc[i][3] = fmaf(a, b.w, acc[i][3]);
        }
    }
#pragma unroll
    for (int i = 0; i < 8; i++)
        *(float4*)&g_G[(long)(rb + ty * 8 + i) * 384 + co + tx * 4] =
            make_float4(acc[i][0], acc[i][1], acc[i][2], acc[i][3]);
}

// ---------------- edge: per-pair bilinear dot + fc1 + log_softmax ----------------
__global__ __launch_bounds__(256) void edge_kernel(int buf, const int* __restrict__ cidx,
                                                   const float* __restrict__ bil_b,
                                                   const float* __restrict__ fc1_W,
                                                   const float* __restrict__ fc1_b,
                                                   float* __restrict__ out) {
    __shared__ float f_s[64][65];
    __shared__ float Gi[4][384];
    __shared__ int cid_s[64];
    __shared__ float s_fc1W[36], s_fc1b[6], s_bilb[6];
    int b = blockIdx.x, it = blockIdx.y, t = threadIdx.x;
    const float* x = g_x[buf];
    if (t < 64) cid_s[t] = cidx[b * 64 + t];
    if (t < 36) s_fc1W[t] = fc1_W[t];
    if (t >= 64 && t < 70) s_fc1b[t - 64] = fc1_b[t - 64];
    if (t >= 96 && t < 102) s_bilb[t - 96] = bil_b[t - 96];
    __syncthreads();
    for (int e = t; e < 4096; e += 256) {
        int m = e >> 6, k = e & 63;
        f_s[m][k] = x[cid_s[m] * DIM + k];
    }
    for (int e = t; e < 1536; e += 256) {
        int i4 = e / 384, ok = e % 384;
        Gi[i4][ok] = g_G[(long)(b * 64 + it * 4 + i4) * 384 + ok];
    }
    __syncthreads();
    int i4 = t >> 6, j = t & 63;
    float ev[6];
#pragma unroll
    for (int o = 0; o < 6; o++) {
        float a = s_bilb[o];
#pragma unroll 16
        for (int k = 0; k < 64; k++) a = fmaf(Gi[i4][o * 64 + k], f_s[j][k], a);
        ev[o] = a;
    }
    float tr[6];
#pragma unroll
    for (int r = 0; r < 6; r++) {
        float a = s_fc1b[r];
#pragma unroll
        for (int o = 0; o < 6; o++) a = fmaf(s_fc1W[r * 6 + o], ev[o], a);
        tr[r] = a;
    }
    float mx = tr[0];
#pragma unroll
    for (int r = 1; r < 6; r++) mx = fmaxf(mx, tr[r]);
    float se = 0.f;
#pragma unroll
    for (int r = 0; r < 6; r++) se += expf(tr[r] - mx);
    float lse = mx + logf(se);
    int pair = (it * 4 + i4) * 64 + j;
    float* op = out + ((long)b * 4096 + pair) * 6;
#pragma unroll
    for (int r = 0; r < 6; r++) op[r] = tr[r] - lse;
}

// ---------------- atom_out = f @ fca_W^T + fca_b ----------------
__global__ __launch_bounds__(96) void atomout_kernel(int buf, const int* __restrict__ cidx,
                                                     const float* __restrict__ fca_b,
                                                     float* __restrict__ out2) {
    __shared__ float xr[64];
    int t = threadIdx.x;
    int r = blockIdx.x;
    int atom = cidx[r];
    if (t < 64) xr[t] = g_x[buf][atom * DIM + t];
    __syncthreads();
    if (t < ORIG) {
        float a = fca_b[t];
#pragma unroll 16
        for (int k = 0; k < 64; k++) a = fmaf(xr[k], g_fcaT[k * ORIG + t], a);
        out2[(long)r * ORIG + t] = a;
    }
}

// ---------------- launch ----------------
#define CONVZ_SM ((KNB * TWO_D + 64 * ASP) * 4)
#define ZS_SM ((64 * TWO_D + 64 * 64) * 4)

extern "C" void kernel_launch(void* const* d_in, const int* in_sizes, int n_in,
                              void* d_out, int out_size) {
    (void)in_sizes; (void)n_in; (void)out_size;
    const float* atom_fea = (const float*)d_in[0];
    const float* nbr_fea  = (const float*)d_in[1];
    const int*   nbr_idx  = (const int*)d_in[2];
    const int*   cidx     = (const int*)d_in[3];
    const float* embed_W  = (const float*)d_in[4];
    const float* conv_W   = (const float*)d_in[5];
    const float* conv_b   = (const float*)d_in[6];
    const float* bn1_g    = (const float*)d_in[7];
    const float* bn1_b    = (const float*)d_in[8];
    const float* bn2_g    = (const float*)d_in[9];
    const float* bn2_b    = (const float*)d_in[10];
    const float* bil_W    = (const float*)d_in[11];
    const float* bil_b    = (const float*)d_in[12];
    const float* fc1_W    = (const float*)d_in[13];
    const float* fc1_b    = (const float*)d_in[14];
    const float* fca_W    = (const float*)d_in[15];
    const float* fca_b    = (const float*)d_in[16];
    float* out = (float*)d_out;

    cudaFuncSetAttribute(convz_kernel, cudaFuncAttributeMaxDynamicSharedMemorySize, CONVZ_SM);
    cudaFuncSetAttribute(zself_kernel, cudaFuncAttributeMaxDynamicSharedMemorySize, ZS_SM);
    cudaFuncSetAttribute(gmat_kernel,  cudaFuncAttributeMaxDynamicSharedMemorySize, ZS_SM);

    prep_kernel<<<(101248 + 255) / 256, 256>>>(conv_W, embed_W, bil_W, fca_W);
    embed_kernel<<<NATOM / 64, 256>>>(atom_fea);

    int buf = 0;
    for (int l = 0; l < 3; l++) {
        zero_stats<<<1, 128>>>();
        zself_kernel<<<NATOM / 64, 256, ZS_SM>>>(l, buf, conv_b);
        convz_kernel<<<(NATOM * MNBR) / 64, 256, CONVZ_SM>>>(l, buf, nbr_fea, nbr_idx);
        reduce_kernel<<<NATOM / 8, 64>>>(l, bn1_g, bn1_b);
        bnres_kernel<<<(NATOM * DIM) / 256, 256>>>(l, buf, bn2_g, bn2_b);
        buf = 1 - buf;
    }

    gmat_kernel<<<dim3(NCRY * NA / 64, 3), 256, ZS_SM>>>(buf, cidx);
    edge_kernel<<<dim3(NCRY, 16), 256>>>(buf, cidx, bil_b, fc1_W, fc1_b, out);
    atomout_kernel<<<NCRY * NA, 96>>>(buf, cidx, fca_b, out + (long)NCRY * NA * NA * 6);
}

// round 2
// speedup vs baseline: 1.0752x; 1.0752x over previous
#include <cuda_runtime.h>
#include <math.h>

#define NATOM 32768
#define MNBR 12
#define DIM 64
#define FNBR 41
#define ORIG 92
#define TWO_D 128
#define KTOT 169
#define KNB 105
#define KNB_P 106
#define KS_P 66
#define KE_P 94
#define NCRY 512
#define NA 64
#define CNT1F (393216.0f)
#define CNT2F (32768.0f)
#define EPSBN 1e-5f

// ---------------- scratch (device globals; no allocation) ----------------
__device__ float g_x[2][NATOM * DIM];
__device__ float g_zself[NATOM * TWO_D];
__device__ float g_z[NATOM * MNBR * TWO_D];          // 201 MB
__device__ float g_summed[NATOM * DIM];
__device__ float g_G[NCRY * NA * 6 * DIM];           // 50 MB
__device__ float g_WtT_s[3 * TWO_D * DIM];           // [l][o][k], k=0..63 (self block)
__device__ float g_WtT_n[3 * TWO_D * KNB_P];         // [l][o][k2], k2=0..105 (nbr block, padded)
__device__ float g_embP[DIM * KE_P];                 // [d][k] padded 94
__device__ float g_bilT2[6 * DIM * KS_P];            // [o*64+kcol][d] padded 66
__device__ float g_fcaT[DIM * ORIG];                 // [k][c]
__device__ float g_s1[TWO_D], g_ss1[TWO_D], g_s2[DIM], g_ss2[DIM];

__device__ __forceinline__ float softplusf(float v) {
    return v > 20.0f ? v : log1pf(expf(v));
}

// ---- packed f32x2 helpers ----
__device__ __forceinline__ unsigned long long pk2(float x, float y) {
    unsigned long long r;
    asm("mov.b64 %0, {%1, %2};" : "=l"(r) : "f"(x), "f"(y));
    return r;
}
__device__ __forceinline__ void ffma2(unsigned long long& p, unsigned long long a,
                                      unsigned long long b) {
    asm("fma.rn.f32x2 %0, %1, %2, %0;" : "+l"(p) : "l"(a), "l"(b));
}
__device__ __forceinline__ float hadd2(unsigned long long v) {
    float x, y;
    asm("mov.b64 {%0, %1}, %2;" : "=f"(x), "=f"(y) : "l"(v));
    return x + y;
}
__device__ __forceinline__ unsigned long long lds64(const float* p) {
    return *reinterpret_cast<const unsigned long long*>(p);
}

// ---------------- prep: K-major padded weight layouts ----------------
__global__ void prep_kernel(const float* __restrict__ conv_W,
                            const float* __restrict__ embed_W,
                            const float* __restrict__ bil_W,
                            const float* __restrict__ fca_W) {
    int idx = blockIdx.x * blockDim.x + threadIdx.x;
    // g_WtT_s: 3*128*64
    if (idx < 3 * TWO_D * DIM) {
        int l = idx / (TWO_D * DIM);
        int r = idx % (TWO_D * DIM);
        int o = r / DIM, k = r % DIM;
        g_WtT_s[idx] = conv_W[(l * TWO_D + o) * KTOT + k];
        return;
    }
    int i1 = idx - 3 * TWO_D * DIM;
    // g_WtT_n: 3*128*106
    if (i1 < 3 * TWO_D * KNB_P) {
        int l = i1 / (TWO_D * KNB_P);
        int r = i1 % (TWO_D * KNB_P);
        int o = r / KNB_P, k2 = r % KNB_P;
        g_WtT_n[i1] = (k2 < KNB) ? conv_W[(l * TWO_D + o) * KTOT + DIM + k2] : 0.f;
        return;
    }
    int i2 = i1 - 3 * TWO_D * KNB_P;
    // g_embP: 64*94
    if (i2 < DIM * KE_P) {
        int d = i2 / KE_P, k = i2 % KE_P;
        g_embP[i2] = (k < ORIG) ? embed_W[d * ORIG + k] : 0.f;
        return;
    }
    int i3 = i2 - DIM * KE_P;
    // g_bilT2: 384*66   value[j][d] = bil_W[o][d][kcol], j = o*64+kcol
    if (i3 < 6 * DIM * KS_P) {
        int j = i3 / KS_P, d = i3 % KS_P;
        int o = j >> 6, kcol = j & 63;
        g_bilT2[i3] = (d < DIM) ? bil_W[(o * DIM + d) * DIM + kcol] : 0.f;
        return;
    }
    int i4 = i3 - 6 * DIM * KS_P;
    if (i4 < DIM * ORIG) {
        int k = i4 / ORIG, c = i4 % ORIG;
        g_fcaT[i4] = fca_W[c * DIM + k];
    }
}

// ---------------- embedding: x = atom_fea @ embed_W^T  (K=92, f32x2) ----------------
__global__ __launch_bounds__(256) void embed_kernel(const float* __restrict__ atom_fea) {
    __shared__ float As[64 * KE_P];
    __shared__ float Ws[DIM * KE_P];
    int t = threadIdx.x;
    int rb = blockIdx.x * 64;
    for (int e = t; e < DIM * KE_P; e += 256) Ws[e] = g_embP[e];
    int warp = t >> 5, lane = t & 31;
    for (int m = warp; m < 64; m += 8) {
        const float* row = atom_fea + (rb + m) * ORIG;
        As[m * KE_P + lane] = row[lane];
        As[m * KE_P + 32 + lane] = row[32 + lane];
        if (lane < ORIG - 64) As[m * KE_P + 64 + lane] = row[64 + lane];
    }
    __syncthreads();
    int ty = t >> 5, tx = t & 31;
    unsigned long long P[8][2];
#pragma unroll
    for (int i = 0; i < 8; i++) { P[i][0] = 0ull; P[i][1] = 0ull; }
    const float* a0 = As + (ty * 8) * KE_P;
#pragma unroll 2
    for (int t2 = 0; t2 < ORIG / 2; t2++) {
        unsigned long long b0 = lds64(&Ws[tx * KE_P + 2 * t2]);
        unsigned long long b1 = lds64(&Ws[(tx + 32) * KE_P + 2 * t2]);
#pragma unroll
        for (int i = 0; i < 8; i++) {
            unsigned long long av = lds64(a0 + i * KE_P + 2 * t2);
            ffma2(P[i][0], av, b0);
            ffma2(P[i][1], av, b1);
        }
    }
#pragma unroll
    for (int i = 0; i < 8; i++) {
        g_x[0][(rb + ty * 8 + i) * DIM + tx]      = hadd2(P[i][0]);
        g_x[0][(rb + ty * 8 + i) * DIM + tx + 32] = hadd2(P[i][1]);
    }
}

// ---------------- per-layer stat zeroing ----------------
__global__ void zero_stats() {
    int t = threadIdx.x;
    if (t < TWO_D) { g_s1[t] = 0.f; g_ss1[t] = 0.f; }
    if (t < DIM)   { g_s2[t] = 0.f; g_ss2[t] = 0.f; }
}

// ---------------- zself[n,o] = b[o] + W[:, :64] . x[n]  (K=64, f32x2) ----------------
__global__ __launch_bounds__(256) void zself_kernel(int l, int buf,
                                                    const float* __restrict__ conv_b) {
    extern __shared__ float sm[];
    float* Ws = sm;                  // [128][66]
    float* As = sm + TWO_D * KS_P;   // [64][66]
    int t = threadIdx.x;
    int rb = blockIdx.x * 64;
    const float* x = g_x[buf];
    for (int e = t; e < TWO_D * DIM; e += 256) {
        int o = e >> 6, k = e & 63;
        Ws[o * KS_P + k] = g_WtT_s[l * TWO_D * DIM + e];
    }
    int warp = t >> 5, lane = t & 31;
    for (int m = warp; m < 64; m += 8) {
        As[m * KS_P + lane]      = x[(rb + m) * DIM + lane];
        As[m * KS_P + 32 + lane] = x[(rb + m) * DIM + 32 + lane];
    }
    __syncthreads();
    int ty = t >> 5, tx = t & 31;
    unsigned long long P[8][4];
#pragma unroll
    for (int i = 0; i < 8; i++)
#pragma unroll
        for (int c = 0; c < 4; c++)
            P[i][c] = pk2(conv_b[l * TWO_D + tx + 32 * c], 0.f);
    const float* a0 = As + (ty * 8) * KS_P;
#pragma unroll 2
    for (int t2 = 0; t2 < 32; t2++) {
        unsigned long long bv[4];
#pragma unroll
        for (int c = 0; c < 4; c++) bv[c] = lds64(&Ws[(tx + 32 * c) * KS_P + 2 * t2]);
#pragma unroll
        for (int i = 0; i < 8; i++) {
            unsigned long long av = lds64(a0 + i * KS_P + 2 * t2);
#pragma unroll
            for (int c = 0; c < 4; c++) ffma2(P[i][c], av, bv[c]);
        }
    }
#pragma unroll
    for (int i = 0; i < 8; i++)
#pragma unroll
        for (int c = 0; c < 4; c++)
            g_zself[(rb + ty * 8 + i) * TWO_D + tx + 32 * c] = hadd2(P[i][c]);
}

// ---------------- main conv GEMM: z = zself + [x[nbr]|nbr_fea] @ W2^T (f32x2) + BN1 stats ----------------
__global__ __launch_bounds__(256) void convz_kernel(int l, int buf,
                                                    const float* __restrict__ nbr_fea,
                                                    const int* __restrict__ nbr_idx) {
    extern __shared__ float sm[];
    float* Ws = sm;                    // [128][106]
    float* As = sm + TWO_D * KNB_P;    // [64][106]
    __shared__ int nbr_s[64];
    int t = threadIdx.x;
    int rb = blockIdx.x * 64;
    const float* x = g_x[buf];
    if (t < 64) nbr_s[t] = nbr_idx[rb + t];
    for (int e = t; e < TWO_D * KNB_P; e += 256)
        Ws[e] = g_WtT_n[l * TWO_D * KNB_P + e];
    __syncthreads();
    int warp = t >> 5, lane = t & 31;
    for (int m = warp; m < 64; m += 8) {
        int nbr = nbr_s[m];
        As[m * KNB_P + lane]      = x[nbr * DIM + lane];
        As[m * KNB_P + 32 + lane] = x[nbr * DIM + 32 + lane];
        const float* nf = nbr_fea + (long)(rb + m) * FNBR;
        As[m * KNB_P + 64 + lane] = nf[lane];
        if (lane < FNBR - 32) As[m * KNB_P + 96 + lane] = nf[32 + lane];
    }
    __syncthreads();
    int ty = t >> 5, tx = t & 31;
    unsigned long long P[8][4];
#pragma unroll
    for (int i = 0; i < 8; i++)
#pragma unroll
        for (int c = 0; c < 4; c++) P[i][c] = 0ull;
    const float* a0 = As + (ty * 8) * KNB_P;
#pragma unroll 2
    for (int t2 = 0; t2 < 52; t2++) {
        unsigned long long bv[4];
#pragma unroll
        for (int c = 0; c < 4; c++) bv[c] = lds64(&Ws[(tx + 32 * c) * KNB_P + 2 * t2]);
#pragma unroll
        for (int i = 0; i < 8; i++) {
            unsigned long long av = lds64(a0 + i * KNB_P + 2 * t2);
#pragma unroll
            for (int c = 0; c < 4; c++) ffma2(P[i][c], av, bv[c]);
        }
    }
    // remainder k = 104 (scalar) + zself + store + stats
    float s[4] = {0.f, 0.f, 0.f, 0.f}, q[4] = {0.f, 0.f, 0.f, 0.f};
#pragma unroll
    for (int i = 0; i < 8; i++) {
        int row = rb + ty * 8 + i;
        int n = row / MNBR;
        float ar = a0[i * KNB_P + 104];
#pragma unroll
        for (int c = 0; c < 4; c++) {
            int col = tx + 32 * c;
            float v = hadd2(P[i][c]) + ar * Ws[col * KNB_P + 104]
                    + g_zself[n * TWO_D + col];
            g_z[(long)row * TWO_D + col] = v;
            s[c] += v; q[c] += v * v;
        }
    }
    __syncthreads();   // As no longer needed; reuse as reduction buffer
    float* redS = As;
    float* redQ = As + 1024;
#pragma unroll
    for (int c = 0; c < 4; c++) {
        redS[ty * TWO_D + tx + 32 * c] = s[c];
        redQ[ty * TWO_D + tx + 32 * c] = q[c];
    }
    __syncthreads();
    if (t < TWO_D) {
        float tot = 0.f;
#pragma unroll
        for (int w = 0; w < 8; w++) tot += redS[w * TWO_D + t];
        atomicAdd(&g_s1[t], tot);
    } else {
        int o = t - TWO_D;
        float tot = 0.f;
#pragma unroll
        for (int w = 0; w < 8; w++) tot += redQ[w * TWO_D + o];
        atomicAdd(&g_ss1[o], tot);
    }
}

// ---------------- BN1 + gate + sum over neighbors, BN2 stats ----------------
__global__ __launch_bounds__(256) void reduce_kernel(int l,
                                                     const float* __restrict__ bn1_g,
                                                     const float* __restrict__ bn1_b) {
    int d = threadIdx.x & 63;
    int grp = threadIdx.x >> 6;
    float inv = 1.0f / CNT1F;
    float mf = g_s1[d] * inv;
    float vf = g_ss1[d] * inv - mf * mf;
    float sc_f = rsqrtf(vf + EPSBN) * bn1_g[l * TWO_D + d];
    float sh_f = bn1_b[l * TWO_D + d] - mf * sc_f;
    float mc = g_s1[64 + d] * inv;
    float vc = g_ss1[64 + d] * inv - mc * mc;
    float sc_c = rsqrtf(vc + EPSBN) * bn1_g[l * TWO_D + 64 + d];
    float sh_c = bn1_b[l * TWO_D + 64 + d] - mc * sc_c;

    float ls = 0.f, lq = 0.f;
    int n0 = blockIdx.x * 16 + grp * 4;
    for (int a = 0; a < 4; a++) {
        int n = n0 + a;
        const float* zr = g_z + (long)n * MNBR * TWO_D;
        float accv = 0.f;
#pragma unroll
        for (int m = 0; m < MNBR; m++) {
            float zf = zr[m * TWO_D + d];
            float zc = zr[m * TWO_D + 64 + d];
            float fv = zf * sc_f + sh_f;
            float cv = zc * sc_c + sh_c;
            float sig = 1.0f / (1.0f + expf(-fv));
            accv += sig * softplusf(cv);
        }
        g_summed[n * DIM + d] = accv;
        ls += accv; lq += accv * accv;
    }
    atomicAdd(&g_s2[d], ls);
    atomicAdd(&g_ss2[d], lq);
}

// ---------------- BN2 + residual softplus -> x_out ----------------
__global__ __launch_bounds__(256) void bnres_kernel(int l, int buf,
                                                    const float* __restrict__ bn2_g,
                                                    const float* __restrict__ bn2_b) {
    int gid = blockIdx.x * 256 + threadIdx.x;
    int d = gid & 63;
    float inv = 1.0f / CNT2F;
    float m2 = g_s2[d] * inv;
    float v2 = g_ss2[d] * inv - m2 * m2;
    float sc = rsqrtf(v2 + EPSBN) * bn2_g[l * DIM + d];
    float sh = bn2_b[l * DIM + d] - m2 * sc;
    float v = g_x[buf][gid] + g_summed[gid] * sc + sh;
    g_x[1 - buf][gid] = softplusf(v);
}

// ---------------- G[bi, j] = f[bi,:] @ bilT2  (K=64, f32x2) ----------------
__global__ __launch_bounds__(256) void gmat_kernel(int buf, const int* __restrict__ cidx) {
    extern __shared__ float sm[];
    float* Ws = sm;                  // [128][66]
    float* As = sm + TWO_D * KS_P;   // [64][66]
    __shared__ int cid_s[64];
    int t = threadIdx.x;
    int rb = blockIdx.x * 64;
    int co = blockIdx.y * 128;
    const float* x = g_x[buf];
    if (t < 64) cid_s[t] = cidx[rb + t];
    for (int e = t; e < TWO_D * KS_P; e += 256) Ws[e] = g_bilT2[co * KS_P + e];
    __syncthreads();
    int warp = t >> 5, lane = t & 31;
    for (int m = warp; m < 64; m += 8) {
        int a = cid_s[m];
        As[m * KS_P + lane]      = x[a * DIM + lane];
        As[m * KS_P + 32 + lane] = x[a * DIM + 32 + lane];
    }
    __syncthreads();
    int ty = t >> 5, tx = t & 31;
    unsigned long long P[8][4];
#pragma unroll
    for (int i = 0; i < 8; i++)
#pragma unroll
        for (int c = 0; c < 4; c++) P[i][c] = 0ull;
    const float* a0 = As + (ty * 8) * KS_P;
#pragma unroll 2
    for (int t2 = 0; t2 < 32; t2++) {
        unsigned long long bv[4];
#pragma unroll
        for (int c = 0; c < 4; c++) bv[c] = lds64(&Ws[(tx + 32 * c) * KS_P + 2 * t2]);
#pragma unroll
        for (int i = 0; i < 8; i++) {
            unsigned long long av = lds64(a0 + i * KS_P + 2 * t2);
#pragma unroll
            for (int c = 0; c < 4; c++) ffma2(P[i][c], av, bv[c]);
        }
    }
#pragma unroll
    for (int i = 0; i < 8; i++)
#pragma unroll
        for (int c = 0; c < 4; c++)
            g_G[(long)(rb + ty * 8 + i) * 384 + co + tx + 32 * c] = hadd2(P[i][c]);
}

// ---------------- edge: per-pair bilinear dot (f32x2) + fc1 + log_softmax ----------------
__global__ __launch_bounds__(256) void edge_kernel(int buf, const int* __restrict__ cidx,
                                                   const float* __restrict__ bil_b,
                                                   const float* __restrict__ fc1_W,
                                                   const float* __restrict__ fc1_b,
                                                   float* __restrict__ out) {
    __shared__ float f_s[64][66];
    __shared__ float Gi[4][384];
    __shared__ int cid_s[64];
    __shared__ float s_fc1W[36], s_fc1b[6], s_bilb[6];
    int b = blockIdx.x, it = blockIdx.y, t = threadIdx.x;
    const float* x = g_x[buf];
    if (t < 64) cid_s[t] = cidx[b * 64 + t];
    if (t < 36) s_fc1W[t] = fc1_W[t];
    if (t >= 64 && t < 70) s_fc1b[t - 64] = fc1_b[t - 64];
    if (t >= 96 && t < 102) s_bilb[t - 96] = bil_b[t - 96];
    __syncthreads();
    for (int e = t; e < 4096; e += 256) {
        int m = e >> 6, k = e & 63;
        f_s[m][k] = x[cid_s[m] * DIM + k];
    }
    for (int e = t; e < 1536; e += 256) {
        int i4 = e / 384, ok = e % 384;
        Gi[i4][ok] = g_G[(long)(b * 64 + it * 4 + i4) * 384 + ok];
    }
    __syncthreads();
    int i4 = t >> 6, j = t & 63;
    unsigned long long P[6];
#pragma unroll
    for (int o = 0; o < 6; o++) P[o] = pk2(s_bilb[o], 0.f);
#pragma unroll 4
    for (int t2 = 0; t2 < 32; t2++) {
        unsigned long long fv = lds64(&f_s[j][2 * t2]);
#pragma unroll
        for (int o = 0; o < 6; o++)
            ffma2(P[o], fv, lds64(&Gi[i4][o * 64 + 2 * t2]));
    }
    float ev[6];
#pragma unroll
    for (int o = 0; o < 6; o++) ev[o] = hadd2(P[o]);
    float tr[6];
#pragma unroll
    for (int r = 0; r < 6; r++) {
        float a = s_fc1b[r];
#pragma unroll
        for (int o = 0; o < 6; o++) a = fmaf(s_fc1W[r * 6 + o], ev[o], a);
        tr[r] = a;
    }
    float mx = tr[0];
#pragma unroll
    for (int r = 1; r < 6; r++) mx = fmaxf(mx, tr[r]);
    float se = 0.f;
#pragma unroll
    for (int r = 0; r < 6; r++) se += expf(tr[r] - mx);
    float lse = mx + logf(se);
    int pair = (it * 4 + i4) * 64 + j;
    float* op = out + ((long)b * 4096 + pair) * 6;
#pragma unroll
    for (int r = 0; r < 6; r++) op[r] = tr[r] - lse;
}

// ---------------- atom_out = f @ fca_W^T + fca_b ----------------
__global__ __launch_bounds__(96) void atomout_kernel(int buf, const int* __restrict__ cidx,
                                                     const float* __restrict__ fca_b,
                                                     float* __restrict__ out2) {
    __shared__ float xr[64];
    int t = threadIdx.x;
    int r = blockIdx.x;
    int atom = cidx[r];
    if (t < 64) xr[t] = g_x[buf][atom * DIM + t];
    __syncthreads();
    if (t < ORIG) {
        float a = fca_b[t];
#pragma unroll 16
        for (int k = 0; k < 64; k++) a = fmaf(xr[k], g_fcaT[k * ORIG + t], a);
        out2[(long)r * ORIG + t] = a;
    }
}

// ---------------- launch ----------------
#define CONVZ_SM ((TWO_D * KNB_P + 64 * KNB_P) * 4)
#define ZS_SM ((TWO_D * KS_P + 64 * KS_P) * 4)

extern "C" void kernel_launch(void* const* d_in, const int* in_sizes, int n_in,
                              void* d_out, int out_size) {
    (void)in_sizes; (void)n_in; (void)out_size;
    const float* atom_fea = (const float*)d_in[0];
    const float* nbr_fea  = (const float*)d_in[1];
    const int*   nbr_idx  = (const int*)d_in[2];
    const int*   cidx     = (const int*)d_in[3];
    const float* embed_W  = (const float*)d_in[4];
    const float* conv_W   = (const float*)d_in[5];
    const float* conv_b   = (const float*)d_in[6];
    const float* bn1_g    = (const float*)d_in[7];
    const float* bn1_b    = (const float*)d_in[8];
    const float* bn2_g    = (const float*)d_in[9];
    const float* bn2_b    = (const float*)d_in[10];
    const float* bil_W    = (const float*)d_in[11];
    const float* bil_b    = (const float*)d_in[12];
    const float* fc1_W    = (const float*)d_in[13];
    const float* fc1_b    = (const float*)d_in[14];
    const float* fca_W    = (const float*)d_in[15];
    const float* fca_b    = (const float*)d_in[16];
    float* out = (float*)d_out;

    cudaFuncSetAttribute(convz_kernel, cudaFuncAttributeMaxDynamicSharedMemorySize, CONVZ_SM);
    cudaFuncSetAttribute(zself_kernel, cudaFuncAttributeMaxDynamicSharedMemorySize, ZS_SM);
    cudaFuncSetAttribute(gmat_kernel,  cudaFuncAttributeMaxDynamicSharedMemorySize, ZS_SM);

    prep_kernel<<<(3 * TWO_D * DIM + 3 * TWO_D * KNB_P + DIM * KE_P + 6 * DIM * KS_P +
                   DIM * ORIG + 255) / 256, 256>>>(conv_W, embed_W, bil_W, fca_W);
    embed_kernel<<<NATOM / 64, 256>>>(atom_fea);

    int buf = 0;
    for (int l = 0; l < 3; l++) {
        zero_stats<<<1, 128>>>();
        zself_kernel<<<NATOM / 64, 256, ZS_SM>>>(l, buf, conv_b);
        convz_kernel<<<(NATOM * MNBR) / 64, 256, CONVZ_SM>>>(l, buf, nbr_fea, nbr_idx);
        reduce_kernel<<<NATOM / 16, 256>>>(l, bn1_g, bn1_b);
        bnres_kernel<<<(NATOM * DIM) / 256, 256>>>(l, buf, bn2_g, bn2_b);
        buf = 1 - buf;
    }

    gmat_kernel<<<dim3(NCRY * NA / 64, 3), 256, ZS_SM>>>(buf, cidx);
    edge_kernel<<<dim3(NCRY, 16), 256>>>(buf, cidx, bil_b, fc1_W, fc1_b, out);
    atomout_kernel<<<NCRY * NA, 96>>>(buf, cidx, fca_b, out + (long)NCRY * NA * NA * 6);
}